// round 13
// baseline (speedup 1.0000x reference)
#include <cuda_runtime.h>
#include <cuda_bf16.h>
#include <cuda_fp16.h>
#include <stdint.h>
#include <math.h>

#define Cc   512
#define Gg   32
#define CPG  16
#define Nn   4096
#define Bb   2
#define EPSf 1e-6f
#define SQf  0.2102241038134287f      // 512^-0.25 (folded into BOTH q and k)

// ---------------- device scratch (static; no runtime alloc) ----------------
__device__ __nv_bfloat16 g_ht[(size_t)Bb * Nn * Cc];    // h  [b][n][c]
__device__ uint8_t       g_q8[(size_t)Bb * Nn * Cc];    // q  e4m3 [b][n][d] (x SQ)
__device__ uint8_t       g_k8[(size_t)Bb * Nn * Cc];    // k  e4m3 [b][n][d] (x SQ)
__device__ uint8_t       g_v8[(size_t)Bb * Cc * Nn];    // v  e4m3 [b][c][n]
__device__ __nv_bfloat16 g_ot[(size_t)Bb * Nn * Cc];    // o  [b][n][c]
__device__ __half        g_s [(size_t)Bb * Nn * Nn];    // scores fp16 [b][i][j]
__device__ uint8_t       g_p8[(size_t)Bb * Nn * Nn];    // probs e4m3 (unnormalized)
__device__ float         g_cr[(size_t)Bb * Nn];         // 1/sum of quantized probs
__device__ __nv_bfloat16 g_wq[Cc * Cc], g_wk[Cc * Cc], g_wv[Cc * Cc], g_wp[Cc * Cc];
__device__ float g_stats[Bb * Gg * 2];

// ---------------- helpers ----------------------------------------------------
__device__ __forceinline__ uint32_t s2u(const void* p) {
    return (uint32_t)__cvta_generic_to_shared((void*)p);
}
__device__ __forceinline__ void cp16(uint32_t saddr, const void* gaddr) {
    asm volatile("cp.async.cg.shared.global [%0], [%1], 16;" :: "r"(saddr), "l"(gaddr));
}
__device__ __forceinline__ void cp_commit() {
    asm volatile("cp.async.commit_group;" ::: "memory");
}
template <int N>
__device__ __forceinline__ void cp_wait() {
    asm volatile("cp.async.wait_group %0;" :: "n"(N) : "memory");
}
__device__ __forceinline__ void ldm4(uint32_t& r0, uint32_t& r1, uint32_t& r2, uint32_t& r3,
                                     uint32_t addr) {
    asm volatile("ldmatrix.sync.aligned.m8n8.x4.shared.b16 {%0,%1,%2,%3}, [%4];"
                 : "=r"(r0), "=r"(r1), "=r"(r2), "=r"(r3) : "r"(addr));
}
__device__ __forceinline__ void mma16816(float* d, const uint32_t* a, const uint32_t* b) {
    asm volatile("mma.sync.aligned.m16n8k16.row.col.f32.bf16.bf16.f32 "
                 "{%0,%1,%2,%3}, {%4,%5,%6,%7}, {%8,%9}, {%0,%1,%2,%3};"
                 : "+f"(d[0]), "+f"(d[1]), "+f"(d[2]), "+f"(d[3])
                 : "r"(a[0]), "r"(a[1]), "r"(a[2]), "r"(a[3]), "r"(b[0]), "r"(b[1]));
}
__device__ __forceinline__ void mma16832q(float* d, const uint32_t* a, const uint32_t* b) {
    asm volatile("mma.sync.aligned.m16n8k32.row.col.f32.e4m3.e4m3.f32 "
                 "{%0,%1,%2,%3}, {%4,%5,%6,%7}, {%8,%9}, {%0,%1,%2,%3};"
                 : "+f"(d[0]), "+f"(d[1]), "+f"(d[2]), "+f"(d[3])
                 : "r"(a[0]), "r"(a[1]), "r"(a[2]), "r"(a[3]), "r"(b[0]), "r"(b[1]));
}
// hi -> upper byte, lo -> lower byte
__device__ __forceinline__ unsigned short f2e4m3x2(float hi, float lo) {
    unsigned short r;
    asm("cvt.rn.satfinite.e4m3x2.f32 %0, %1, %2;" : "=h"(r) : "f"(hi), "f"(lo));
    return r;
}
__device__ __forceinline__ uint32_t e4m3x2_2h(unsigned short s) {
    uint32_t r;
    asm("cvt.rn.f16x2.e4m3x2 %0, %1;" : "=r"(r) : "h"(s));
    return r;
}
// SW128 swizzle for 128B rows: element (row, 16B-chunk c in 0..7)
__device__ __forceinline__ uint32_t smoff(int row, int c) {
    return (uint32_t)(row * 128 + ((c ^ (row & 7)) << 4));
}
__device__ __forceinline__ float fexp(float x) {
    x = fmaxf(x, -87.f);
    float z  = x * 1.4426950408889634f;
    float zi = rintf(z);
    float zf = z - zi;
    float r = 1.33978439e-3f;
    r = fmaf(r, zf, 9.67580429e-3f);
    r = fmaf(r, zf, 5.55041087e-2f);
    r = fmaf(r, zf, 2.40226507e-1f);
    r = fmaf(r, zf, 6.93147182e-1f);
    r = fmaf(r, zf, 1.0f);
    return r * __int_as_float(((int)zi + 127) << 23);
}

// ---------------- weight fp32 -> bf16 ---------------------------------------
__global__ void conv_w_kernel(const float* __restrict__ a, const float* __restrict__ b,
                              const float* __restrict__ c, const float* __restrict__ d,
                              __nv_bfloat16* oa, __nv_bfloat16* ob,
                              __nv_bfloat16* oc, __nv_bfloat16* od) {
    int i = blockIdx.x * blockDim.x + threadIdx.x;
    const float4* src[4] = {(const float4*)a, (const float4*)b, (const float4*)c, (const float4*)d};
    __nv_bfloat162* dst[4] = {(__nv_bfloat162*)oa, (__nv_bfloat162*)ob,
                              (__nv_bfloat162*)oc, (__nv_bfloat162*)od};
    #pragma unroll
    for (int m = 0; m < 4; m++) {
        float4 v = src[m][i];
        dst[m][i * 2 + 0] = __nv_bfloat162(__float2bfloat16(v.x), __float2bfloat16(v.y));
        dst[m][i * 2 + 1] = __nv_bfloat162(__float2bfloat16(v.z), __float2bfloat16(v.w));
    }
}

// ---------------- GroupNorm stats -------------------------------------------
__global__ void gn_stats_kernel(const float* __restrict__ x, float* __restrict__ stats) {
    const int bg = blockIdx.x;
    const size_t base = (size_t)bg * CPG * Nn;
    const int n_el = CPG * Nn;
    float s = 0.f, ss = 0.f;
    for (int i = threadIdx.x; i < n_el; i += blockDim.x) {
        float v = x[base + i];
        s += v; ss += v * v;
    }
    __shared__ float red[16];
    #pragma unroll
    for (int o = 16; o; o >>= 1) {
        s  += __shfl_down_sync(0xffffffffu, s,  o);
        ss += __shfl_down_sync(0xffffffffu, ss, o);
    }
    const int wid = threadIdx.x >> 5, lane = threadIdx.x & 31;
    if (lane == 0) { red[wid] = s; red[8 + wid] = ss; }
    __syncthreads();
    if (threadIdx.x == 0) {
        float ts = 0.f, tss = 0.f;
        #pragma unroll
        for (int i = 0; i < 8; i++) { ts += red[i]; tss += red[8 + i]; }
        float mu = ts / (float)n_el;
        float var = tss / (float)n_el - mu * mu;
        stats[bg * 2 + 0] = mu;
        stats[bg * 2 + 1] = rsqrtf(var + EPSf);
    }
}

// ---------------- normalize + transpose x[b][c][n] -> h[b][n][c] bf16 -------
__global__ void gn_norm_t_kernel(const float* __restrict__ x,
                                 const float* __restrict__ w, const float* __restrict__ b,
                                 const float* __restrict__ stats,
                                 __nv_bfloat16* __restrict__ ht) {
    __shared__ float tile[64][65];
    const int n0 = blockIdx.x * 64, c0 = blockIdx.y * 64, bz = blockIdx.z;
    const int tid = threadIdx.x;
    const float* xb = x + (size_t)bz * Cc * Nn;
    #pragma unroll
    for (int i = 0; i < 4; i++) {
        int vi = tid + i * 256;
        int r = vi >> 4, seg = (vi & 15) * 4;
        float4 v = *(const float4*)&xb[(size_t)(c0 + r) * Nn + n0 + seg];
        tile[r][seg + 0] = v.x; tile[r][seg + 1] = v.y;
        tile[r][seg + 2] = v.z; tile[r][seg + 3] = v.w;
    }
    __syncthreads();
    const int nr = tid >> 2, cs = (tid & 3) * 16;
    __nv_bfloat16* hrow = ht + ((size_t)bz * Nn + n0 + nr) * Cc + c0;
    #pragma unroll
    for (int c = 0; c < 16; c++) {
        int cg = cs + c, ch = c0 + cg;
        int sidx = (bz * Gg + (ch >> 4)) * 2;
        float mu = stats[sidx], inv = stats[sidx + 1];
        hrow[cg] = __float2bfloat16((tile[cg][nr] - mu) * inv * w[ch] + b[ch]);
    }
}

// ============ bf16 GEMM (fp32 acc): C[M][N] = A[M][K] @ B[N][K]^T ============
// Tile 128x256x64, 512 threads (16 warps, 4x4), warp tile 32x64, 3 stages.
// MQK: out = e4m3((acc+bias[col])*SQ).  MV: out = e4m3(acc+bias[row]).
// MP : out = fp32 acc + bias[row] + resid.
enum { MQK = 0, MV = 2, MP = 5 };
#define BKg 64
#define STAGES 3
#define A_BYTES 16384
#define B_BYTES 32768
#define STG_BYTES (A_BYTES + B_BYTES)
#define GEMM_SMEM (STAGES * STG_BYTES)       // 144 KB

template <int MODE>
__global__ __launch_bounds__(512, 1)
void hgemm(const __nv_bfloat16* __restrict__ A, const __nv_bfloat16* __restrict__ B,
           void* __restrict__ OutP, int lda, int ldb, int Nd, int K,
           const float* __restrict__ bias, const float* __restrict__ resid,
           long long sA, long long sB, long long sO, long long sR) {
    extern __shared__ char smem[];
    const uint32_t sbase = s2u(smem);
    const int tid = threadIdx.x, lane = tid & 31, warp = tid >> 5;
    const int wmB = (warp >> 2) * 32, wnB = (warp & 3) * 64;
    const int m0 = blockIdx.y * 128, n0 = blockIdx.x * 256;
    const int bz = blockIdx.z;

    const int rr = tid >> 3, cch = tid & 7;
    const uint32_t sof = smoff(rr, cch);
    const __nv_bfloat16* pA = A + (size_t)bz * sA + (size_t)(m0 + rr) * lda + cch * 8;
    const __nv_bfloat16* pB = B + (size_t)bz * sB + (size_t)(n0 + rr) * ldb + cch * 8;
    const size_t strA = (size_t)64 * lda, strB = (size_t)64 * ldb;

    const int NT = K / BKg;
    #pragma unroll
    for (int t = 0; t < STAGES - 1; t++) {
        if (t < NT) {
            uint32_t sa = sbase + t * STG_BYTES;
            const __nv_bfloat16* a_src = pA + t * BKg;
            const __nv_bfloat16* b_src = pB + t * BKg;
            cp16(sa + sof,        a_src);
            cp16(sa + sof + 8192, a_src + strA);
            #pragma unroll
            for (int i = 0; i < 4; i++)
                cp16(sa + A_BYTES + sof + 8192 * i, b_src + strB * i);
        }
        cp_commit();
    }

    float acc[2][8][4];
    #pragma unroll
    for (int i = 0; i < 2; i++)
        #pragma unroll
        for (int j = 0; j < 8; j++)
            #pragma unroll
            for (int k = 0; k < 4; k++) acc[i][j][k] = 0.f;

    const int aRow = lane & 15, aC = lane >> 4;
    const int bRow = (lane & 7) + ((lane & 16) >> 1), bC = (lane >> 3) & 1;

    for (int t = 0; t < NT; t++) {
        if (t >= NT - (STAGES - 1)) cp_wait<0>(); else cp_wait<STAGES - 2>();
        __syncthreads();
        if (t + STAGES - 1 < NT) {
            int tp = t + STAGES - 1;
            uint32_t sa = sbase + (tp % STAGES) * STG_BYTES;
            const __nv_bfloat16* a_src = pA + tp * BKg;
            const __nv_bfloat16* b_src = pB + tp * BKg;
            cp16(sa + sof,        a_src);
            cp16(sa + sof + 8192, a_src + strA);
            #pragma unroll
            for (int i = 0; i < 4; i++)
                cp16(sa + A_BYTES + sof + 8192 * i, b_src + strB * i);
        }
        cp_commit();
        const uint32_t aS = sbase + (t % STAGES) * STG_BYTES;
        const uint32_t bS = aS + A_BYTES;
        #pragma unroll
        for (int kk = 0; kk < 4; kk++) {
            uint32_t af[2][4], bf[8][2];
            #pragma unroll
            for (int mf = 0; mf < 2; mf++)
                ldm4(af[mf][0], af[mf][1], af[mf][2], af[mf][3],
                     aS + smoff(wmB + mf * 16 + aRow, kk * 2 + aC));
            #pragma unroll
            for (int g = 0; g < 4; g++)
                ldm4(bf[2 * g][0], bf[2 * g][1], bf[2 * g + 1][0], bf[2 * g + 1][1],
                     bS + smoff(wnB + g * 16 + bRow, kk * 2 + bC));
            #pragma unroll
            for (int mf = 0; mf < 2; mf++)
                #pragma unroll
                for (int nf = 0; nf < 8; nf++)
                    mma16816(acc[mf][nf], af[mf], bf[nf]);
        }
    }

    float* Of = (float*)OutP + (size_t)bz * sO;
    uint8_t* O8 = (uint8_t*)OutP + (size_t)bz * sO;
    const float* Rz = resid + (size_t)bz * sR;
    #pragma unroll
    for (int mf = 0; mf < 2; mf++) {
        #pragma unroll
        for (int pr = 0; pr < 2; pr++) {
            const int row = m0 + wmB + mf * 16 + (lane >> 2) + pr * 8;
            float rb = 0.f;
            if (MODE == MV || MODE == MP) rb = bias[row];
            #pragma unroll
            for (int nf = 0; nf < 8; nf++) {
                const int col = n0 + wnB + nf * 8 + (lane & 3) * 2;
                float v0 = acc[mf][nf][pr * 2 + 0];
                float v1 = acc[mf][nf][pr * 2 + 1];
                const size_t oi = (size_t)row * Nd + col;
                if (MODE == MQK) {
                    v0 = (v0 + bias[col]) * SQf;
                    v1 = (v1 + bias[col + 1]) * SQf;
                    *(unsigned short*)&O8[oi] = f2e4m3x2(v1, v0);
                } else if (MODE == MV) {
                    *(unsigned short*)&O8[oi] = f2e4m3x2(v1 + rb, v0 + rb);
                } else {
                    float2 rrv = *(const float2*)&Rz[oi];
                    *(float2*)&Of[oi] = make_float2(v0 + rb + rrv.x, v1 + rb + rrv.y);
                }
            }
        }
    }
}

// ============ fp8 GEMM (e4m3, fp32 acc): C[M][N] = A[M][K] @ B[N][K]^T =======
// Tile 128x256x128(K fp8), 512 threads (4x4 warps), warp tile 32x64, 3 stages.
// lda/ldb in BYTES (=fp8 elements). OUT=0: fp16 scores. OUT=1: bf16 o, x corr[row].
template <int OUT>
__global__ __launch_bounds__(512, 1)
void hgemm8(const uint8_t* __restrict__ A, const uint8_t* __restrict__ B,
            void* __restrict__ OutP, int lda, int ldb, int Nd, int K,
            const float* __restrict__ corr,
            long long sA, long long sB, long long sO) {
    extern __shared__ char smem[];
    const uint32_t sbase = s2u(smem);
    const int tid = threadIdx.x, lane = tid & 31, warp = tid >> 5;
    const int wmB = (warp >> 2) * 32, wnB = (warp & 3) * 64;
    const int m0 = blockIdx.y * 128, n0 = blockIdx.x * 256;
    const int bz = blockIdx.z;

    const int rr = tid >> 3, cch = tid & 7;
    const uint32_t sof = smoff(rr, cch);
    const uint8_t* pA = A + (size_t)bz * sA + (size_t)(m0 + rr) * lda + cch * 16;
    const uint8_t* pB = B + (size_t)bz * sB + (size_t)(n0 + rr) * ldb + cch * 16;
    const size_t strA = (size_t)64 * lda, strB = (size_t)64 * ldb;

    const int NT = K / 128;                 // k-tile = 128 fp8
    #pragma unroll
    for (int t = 0; t < STAGES - 1; t++) {
        if (t < NT) {
            uint32_t sa = sbase + t * STG_BYTES;
            const uint8_t* a_src = pA + t * 128;
            const uint8_t* b_src = pB + t * 128;
            cp16(sa + sof,        a_src);
            cp16(sa + sof + 8192, a_src + strA);
            #pragma unroll
            for (int i = 0; i < 4; i++)
                cp16(sa + A_BYTES + sof + 8192 * i, b_src + strB * i);
        }
        cp_commit();
    }

    float acc[2][8][4];
    #pragma unroll
    for (int i = 0; i < 2; i++)
        #pragma unroll
        for (int j = 0; j < 8; j++)
            #pragma unroll
            for (int k = 0; k < 4; k++) acc[i][j][k] = 0.f;

    const int aRow = lane & 15, aC = lane >> 4;
    const int bRow = (lane & 7) + ((lane & 16) >> 1), bC = (lane >> 3) & 1;

    for (int t = 0; t < NT; t++) {
        if (t >= NT - (STAGES - 1)) cp_wait<0>(); else cp_wait<STAGES - 2>();
        __syncthreads();
        if (t + STAGES - 1 < NT) {
            int tp = t + STAGES - 1;
            uint32_t sa = sbase + (tp % STAGES) * STG_BYTES;
            const uint8_t* a_src = pA + tp * 128;
            const uint8_t* b_src = pB + tp * 128;
            cp16(sa + sof,        a_src);
            cp16(sa + sof + 8192, a_src + strA);
            #pragma unroll
            for (int i = 0; i < 4; i++)
                cp16(sa + A_BYTES + sof + 8192 * i, b_src + strB * i);
        }
        cp_commit();
        const uint32_t aS = sbase + (t % STAGES) * STG_BYTES;
        const uint32_t bS = aS + A_BYTES;
        // 4 k-steps of 32 fp8 each (one 32B = 2 swizzle chunks per step)
        #pragma unroll
        for (int kk = 0; kk < 4; kk++) {
            uint32_t af[2][4], bf[8][2];
            #pragma unroll
            for (int mf = 0; mf < 2; mf++)
                ldm4(af[mf][0], af[mf][1], af[mf][2], af[mf][3],
                     aS + smoff(wmB + mf * 16 + aRow, kk * 2 + aC));
            #pragma unroll
            for (int g = 0; g < 4; g++)
                ldm4(bf[2 * g][0], bf[2 * g][1], bf[2 * g + 1][0], bf[2 * g + 1][1],
                     bS + smoff(wnB + g * 16 + bRow, kk * 2 + bC));
            #pragma unroll
            for (int mf = 0; mf < 2; mf++)
                #pragma unroll
                for (int nf = 0; nf < 8; nf++)
                    mma16832q(acc[mf][nf], af[mf], bf[nf]);
        }
    }

    __half* Oh = (__half*)OutP + (size_t)bz * sO;
    __nv_bfloat16* Ob = (__nv_bfloat16*)OutP + (size_t)bz * sO;
    #pragma unroll
    for (int mf = 0; mf < 2; mf++) {
        #pragma unroll
        for (int pr = 0; pr < 2; pr++) {
            const int row = m0 + wmB + mf * 16 + (lane >> 2) + pr * 8;
            float cr = 1.f;
            if (OUT == 1) cr = corr[(size_t)bz * Nn + row];
            #pragma unroll
            for (int nf = 0; nf < 8; nf++) {
                const int col = n0 + wnB + nf * 8 + (lane & 3) * 2;
                float v0 = acc[mf][nf][pr * 2 + 0];
                float v1 = acc[mf][nf][pr * 2 + 1];
                const size_t oi = (size_t)row * Nd + col;
                if (OUT == 0) {
                    *(__half2*)&Oh[oi] = __floats2half2_rn(v0, v1);
                } else {
                    *(__nv_bfloat162*)&Ob[oi] =
                        __nv_bfloat162(__float2bfloat16(v0 * cr), __float2bfloat16(v1 * cr));
                }
            }
        }
    }
}

// ------- softmax: fp16 scores -> unnormalized e4m3 probs + 1/sum(quantized) --
__global__ void softmax8_kernel(const __half* __restrict__ s,
                                uint8_t* __restrict__ p8, float* __restrict__ corr) {
    const size_t row = blockIdx.x;
    const __half* p = s + row * Nn;
    uint8_t* o = p8 + row * Nn;
    const int tid = threadIdx.x;

    float v[16];
    uint4 r0 = *(const uint4*)(p + tid * 16);
    uint4 r1 = *(const uint4*)(p + tid * 16 + 8);
    {
        const __half* h0 = (const __half*)&r0;
        const __half* h1 = (const __half*)&r1;
        #pragma unroll
        for (int e = 0; e < 8; e++) { v[e] = __half2float(h0[e]); v[8 + e] = __half2float(h1[e]); }
    }
    float mx = -1e30f;
    #pragma unroll
    for (int i = 0; i < 16; i++) mx = fmaxf(mx, v[i]);
    __shared__ float red[8];
    const int wid = tid >> 5, lane = tid & 31;
    #pragma unroll
    for (int off = 16; off; off >>= 1) mx = fmaxf(mx, __shfl_xor_sync(0xffffffffu, mx, off));
    if (lane == 0) red[wid] = mx;
    __syncthreads();
    mx = red[0];
    #pragma unroll
    for (int i = 1; i < 8; i++) mx = fmaxf(mx, red[i]);
    __syncthreads();

    // quantize unnormalized exp values; sum the QUANTIZED values
    unsigned short q[8];
    float sum = 0.f;
    #pragma unroll
    for (int i = 0; i < 8; i++) {
        float e0 = fexp(v[2 * i] - mx);
        float e1 = fexp(v[2 * i + 1] - mx);
        q[i] = f2e4m3x2(e1, e0);
        uint32_t hh = e4m3x2_2h(q[i]);
        float2 de = __half22float2(*(__half2*)&hh);
        sum += de.x + de.y;
    }
    #pragma unroll
    for (int off = 16; off; off >>= 1) sum += __shfl_xor_sync(0xffffffffu, sum, off);
    if (lane == 0) red[wid] = sum;
    __syncthreads();
    if (tid == 0) {
        float ts = 0.f;
        #pragma unroll
        for (int i = 0; i < 8; i++) ts += red[i];
        corr[row] = 1.f / ts;
    }
    uint4 outp;
    unsigned short* os = (unsigned short*)&outp;
    #pragma unroll
    for (int i = 0; i < 8; i++) os[i] = q[i];
    *(uint4*)(o + tid * 16) = outp;
}

// ---------------- launch -----------------------------------------------------
extern "C" void kernel_launch(void* const* d_in, const int* in_sizes, int n_in,
                              void* d_out, int out_size) {
    const float* x  = (const float*)d_in[0];
    const float* gw = (const float*)d_in[1];
    const float* gb = (const float*)d_in[2];
    const float* wq = (const float*)d_in[3];
    const float* bq = (const float*)d_in[4];
    const float* wk = (const float*)d_in[5];
    const float* bk = (const float*)d_in[6];
    const float* wv = (const float*)d_in[7];
    const float* bv = (const float*)d_in[8];
    const float* wp = (const float*)d_in[9];
    const float* bp = (const float*)d_in[10];
    float* out = (float*)d_out;

    __nv_bfloat16 *ht, *ot, *bwq, *bwk, *bwv, *bwp;
    uint8_t *q8, *k8, *v8, *p8;
    __half* sc;
    float *stats, *cr;
    cudaGetSymbolAddress((void**)&ht, g_ht);
    cudaGetSymbolAddress((void**)&q8, g_q8);
    cudaGetSymbolAddress((void**)&k8, g_k8);
    cudaGetSymbolAddress((void**)&v8, g_v8);
    cudaGetSymbolAddress((void**)&ot, g_ot);
    cudaGetSymbolAddress((void**)&sc, g_s);
    cudaGetSymbolAddress((void**)&p8, g_p8);
    cudaGetSymbolAddress((void**)&cr, g_cr);
    cudaGetSymbolAddress((void**)&bwq, g_wq);
    cudaGetSymbolAddress((void**)&bwk, g_wk);
    cudaGetSymbolAddress((void**)&bwv, g_wv);
    cudaGetSymbolAddress((void**)&bwp, g_wp);
    cudaGetSymbolAddress((void**)&stats, g_stats);

    cudaFuncSetAttribute(hgemm<MQK>, cudaFuncAttributeMaxDynamicSharedMemorySize, GEMM_SMEM);
    cudaFuncSetAttribute(hgemm<MV>,  cudaFuncAttributeMaxDynamicSharedMemorySize, GEMM_SMEM);
    cudaFuncSetAttribute(hgemm<MP>,  cudaFuncAttributeMaxDynamicSharedMemorySize, GEMM_SMEM);
    cudaFuncSetAttribute(hgemm8<0>,  cudaFuncAttributeMaxDynamicSharedMemorySize, GEMM_SMEM);
    cudaFuncSetAttribute(hgemm8<1>,  cudaFuncAttributeMaxDynamicSharedMemorySize, GEMM_SMEM);

    const long long NC_ = (long long)Nn * Cc;
    const long long CN_ = (long long)Cc * Nn;
    const long long NN_ = (long long)Nn * Nn;

    conv_w_kernel<<<256, 256>>>(wq, wk, wv, wp, bwq, bwk, bwv, bwp);
    gn_stats_kernel<<<Bb * Gg, 256>>>(x, stats);
    gn_norm_t_kernel<<<dim3(Nn / 64, Cc / 64, Bb), 256>>>(x, gw, gb, stats, ht);

    // q8[n][d] = e4m3(SQ*(h@Wq + bq)); k8 likewise            M=4096 N=512 K=512
    hgemm<MQK><<<dim3(2, 32, Bb), 512, GEMM_SMEM>>>(ht, bwq, q8, Cc, Cc, Cc, Cc,
                                                    bq, nullptr, NC_, 0, NC_, 0);
    hgemm<MQK><<<dim3(2, 32, Bb), 512, GEMM_SMEM>>>(ht, bwk, k8, Cc, Cc, Cc, Cc,
                                                    bk, nullptr, NC_, 0, NC_, 0);
    // v8[c][n] = e4m3(Wv@h + bv)                              M=512 N=4096 K=512
    hgemm<MV><<<dim3(16, 4, Bb), 512, GEMM_SMEM>>>(bwv, ht, v8, Cc, Cc, Nn, Cc,
                                                   bv, nullptr, 0, NC_, CN_, 0);
    // s[i][j] = q8[i]·k8[j]  (fp8 mma, fp32 acc, fp16 out)    M=4096 N=4096 K=512
    hgemm8<0><<<dim3(16, 32, Bb), 512, GEMM_SMEM>>>(q8, k8, sc, Cc, Cc, Nn, Cc,
                                                    nullptr, NC_, NC_, NN_);
    softmax8_kernel<<<Bb * Nn, 256>>>(sc, p8, cr);
    // o[q][c] = corr[q] * Σ p8[q][j] v8[c][j]  (fp8 mma)      M=4096 N=512 K=4096
    hgemm8<1><<<dim3(2, 32, Bb), 512, GEMM_SMEM>>>(p8, v8, ot, Nn, Nn, Cc, Nn,
                                                   cr, NN_, CN_, NC_);
    // out[c][n] = Wp@o + bp + x                               M=512 N=4096 K=512
    hgemm<MP><<<dim3(16, 4, Bb), 512, GEMM_SMEM>>>(bwp, ot, out, Cc, Cc, Nn, Cc,
                                                   bp, x, 0, NC_, CN_, CN_);
}

// round 14
// speedup vs baseline: 1.0971x; 1.0971x over previous
#include <cuda_runtime.h>
#include <cuda_bf16.h>
#include <stdint.h>
#include <math.h>

#define Cc   512
#define Gg   32
#define CPG  16
#define Nn   4096
#define Bb   2
#define EPSf 1e-6f
#define SCALEf 0.04419417382415922f   // 512^-0.5

// ---------------- device scratch (static; no runtime alloc) ----------------
__device__ __nv_bfloat16 g_ht[(size_t)Bb * Nn * Cc];   // h  [b][n][c]
__device__ __nv_bfloat16 g_qt[(size_t)Bb * Nn * Cc];   // q  [b][n][d] (pre-scaled)
__device__ __nv_bfloat16 g_kt[(size_t)Bb * Nn * Cc];   // k  [b][n][d]
__device__ __nv_bfloat16 g_vv[(size_t)Bb * Cc * Nn];   // v  [b][c][n]
__device__ __nv_bfloat16 g_ot[(size_t)Bb * Nn * Cc];   // o  [b][n][c]
__device__ __nv_bfloat16 g_s [(size_t)Bb * Nn * Nn];   // scores / probs [b][i][j]
__device__ __nv_bfloat16 g_wq[Cc * Cc], g_wk[Cc * Cc], g_wv[Cc * Cc], g_wp[Cc * Cc];
__device__ float g_stats[Bb * Gg * 2];

// ---------------- helpers ----------------------------------------------------
__device__ __forceinline__ uint32_t s2u(const void* p) {
    return (uint32_t)__cvta_generic_to_shared((void*)p);
}
__device__ __forceinline__ void cp16(uint32_t saddr, const void* gaddr) {
    asm volatile("cp.async.cg.shared.global [%0], [%1], 16;" :: "r"(saddr), "l"(gaddr));
}
__device__ __forceinline__ void cp_commit() {
    asm volatile("cp.async.commit_group;" ::: "memory");
}
template <int N>
__device__ __forceinline__ void cp_wait() {
    asm volatile("cp.async.wait_group %0;" :: "n"(N) : "memory");
}
__device__ __forceinline__ void ldm4(uint32_t& r0, uint32_t& r1, uint32_t& r2, uint32_t& r3,
                                     uint32_t addr) {
    asm volatile("ldmatrix.sync.aligned.m8n8.x4.shared.b16 {%0,%1,%2,%3}, [%4];"
                 : "=r"(r0), "=r"(r1), "=r"(r2), "=r"(r3) : "r"(addr));
}
__device__ __forceinline__ void mma16816(float* d, const uint32_t* a, const uint32_t* b) {
    asm volatile("mma.sync.aligned.m16n8k16.row.col.f32.bf16.bf16.f32 "
                 "{%0,%1,%2,%3}, {%4,%5,%6,%7}, {%8,%9}, {%0,%1,%2,%3};"
                 : "+f"(d[0]), "+f"(d[1]), "+f"(d[2]), "+f"(d[3])
                 : "r"(a[0]), "r"(a[1]), "r"(a[2]), "r"(a[3]), "r"(b[0]), "r"(b[1]));
}
// SW128 swizzle for 128B rows: element (row, 16B-chunk c in 0..7)
__device__ __forceinline__ uint32_t smoff(int row, int c) {
    return (uint32_t)(row * 128 + ((c ^ (row & 7)) << 4));
}
__device__ __forceinline__ float fexp(float x) {
    x = fmaxf(x, -87.f);
    float z  = x * 1.4426950408889634f;
    float zi = rintf(z);
    float zf = z - zi;
    float r = 1.33978439e-3f;
    r = fmaf(r, zf, 9.67580429e-3f);
    r = fmaf(r, zf, 5.55041087e-2f);
    r = fmaf(r, zf, 2.40226507e-1f);
    r = fmaf(r, zf, 6.93147182e-1f);
    r = fmaf(r, zf, 1.0f);
    return r * __int_as_float(((int)zi + 127) << 23);
}

// ---------------- fused weight-convert + GroupNorm stats --------------------
// blocks [0,256): fp32->bf16 of 4 weight mats; blocks [256,320): per-(b,g) stats
__global__ void prep_kernel(const float* __restrict__ wq, const float* __restrict__ wk,
                            const float* __restrict__ wv, const float* __restrict__ wp,
                            __nv_bfloat16* oq, __nv_bfloat16* ok,
                            __nv_bfloat16* ov, __nv_bfloat16* op,
                            const float* __restrict__ x, float* __restrict__ stats) {
    if (blockIdx.x < 256) {
        int i = blockIdx.x * blockDim.x + threadIdx.x;
        const float4* src[4] = {(const float4*)wq, (const float4*)wk,
                                (const float4*)wv, (const float4*)wp};
        __nv_bfloat162* dst[4] = {(__nv_bfloat162*)oq, (__nv_bfloat162*)ok,
                                  (__nv_bfloat162*)ov, (__nv_bfloat162*)op};
        #pragma unroll
        for (int m = 0; m < 4; m++) {
            float4 v = src[m][i];
            dst[m][i * 2 + 0] = __nv_bfloat162(__float2bfloat16(v.x), __float2bfloat16(v.y));
            dst[m][i * 2 + 1] = __nv_bfloat162(__float2bfloat16(v.z), __float2bfloat16(v.w));
        }
        return;
    }
    const int bg = blockIdx.x - 256;
    const size_t base = (size_t)bg * CPG * Nn;
    const int n_el = CPG * Nn;
    float s = 0.f, ss = 0.f;
    for (int i = threadIdx.x; i < n_el; i += blockDim.x) {
        float v = x[base + i];
        s += v; ss += v * v;
    }
    __shared__ float red[16];
    #pragma unroll
    for (int o = 16; o; o >>= 1) {
        s  += __shfl_down_sync(0xffffffffu, s,  o);
        ss += __shfl_down_sync(0xffffffffu, ss, o);
    }
    const int wid = threadIdx.x >> 5, lane = threadIdx.x & 31;
    if (lane == 0) { red[wid] = s; red[8 + wid] = ss; }
    __syncthreads();
    if (threadIdx.x == 0) {
        float ts = 0.f, tss = 0.f;
        #pragma unroll
        for (int i = 0; i < 8; i++) { ts += red[i]; tss += red[8 + i]; }
        float mu = ts / (float)n_el;
        float var = tss / (float)n_el - mu * mu;
        stats[bg * 2 + 0] = mu;
        stats[bg * 2 + 1] = rsqrtf(var + EPSf);
    }
}

// ---------------- normalize + transpose x[b][c][n] -> h[b][n][c] bf16 -------
__global__ void gn_norm_t_kernel(const float* __restrict__ x,
                                 const float* __restrict__ w, const float* __restrict__ b,
                                 const float* __restrict__ stats,
                                 __nv_bfloat16* __restrict__ ht) {
    __shared__ float tile[64][65];
    const int n0 = blockIdx.x * 64, c0 = blockIdx.y * 64, bz = blockIdx.z;
    const int tid = threadIdx.x;
    const float* xb = x + (size_t)bz * Cc * Nn;
    #pragma unroll
    for (int i = 0; i < 4; i++) {
        int vi = tid + i * 256;
        int r = vi >> 4, seg = (vi & 15) * 4;
        float4 v = *(const float4*)&xb[(size_t)(c0 + r) * Nn + n0 + seg];
        tile[r][seg + 0] = v.x; tile[r][seg + 1] = v.y;
        tile[r][seg + 2] = v.z; tile[r][seg + 3] = v.w;
    }
    __syncthreads();
    const int nr = tid >> 2, cs = (tid & 3) * 16;
    __nv_bfloat16* hrow = ht + ((size_t)bz * Nn + n0 + nr) * Cc + c0;
    #pragma unroll
    for (int c = 0; c < 16; c++) {
        int cg = cs + c, ch = c0 + cg;
        int sidx = (bz * Gg + (ch >> 4)) * 2;
        float mu = stats[sidx], inv = stats[sidx + 1];
        hrow[cg] = __float2bfloat16((tile[cg][nr] - mu) * inv * w[ch] + b[ch]);
    }
}

// ---------------- generic bf16 HMMA GEMM (R9 config) -------------------------
// Tile 128(M) x 256(N) x 64(K), 512 threads (16 warps, 4x4), warp tile 32x64.
enum { MQ = 0, MK = 1, MV = 2, MS = 3, MA = 4, MP = 5 };
#define BKg 64
#define STAGES 3
#define A_BYTES 16384
#define B_BYTES 32768
#define STG_BYTES (A_BYTES + B_BYTES)
#define GEMM_SMEM (STAGES * STG_BYTES)       // 144 KB

template <int MODE>
__global__ __launch_bounds__(512, 1)
void hgemm(const __nv_bfloat16* __restrict__ A, const __nv_bfloat16* __restrict__ B,
           void* __restrict__ OutP, int lda, int ldb, int Nd, int K,
           const float* __restrict__ bias, const float* __restrict__ resid,
           long long sA, long long sB, long long sO, long long sR) {
    extern __shared__ char smem[];
    const uint32_t sbase = s2u(smem);
    const int tid = threadIdx.x, lane = tid & 31, warp = tid >> 5;
    const int wmB = (warp >> 2) * 32, wnB = (warp & 3) * 64;
    const int m0 = blockIdx.y * 128, n0 = blockIdx.x * 256;
    const int bz = blockIdx.z;

    const int rr = tid >> 3, cch = tid & 7;
    const uint32_t sof = smoff(rr, cch);
    const __nv_bfloat16* pA = A + (size_t)bz * sA + (size_t)(m0 + rr) * lda + cch * 8;
    const __nv_bfloat16* pB = B + (size_t)bz * sB + (size_t)(n0 + rr) * ldb + cch * 8;
    const size_t strA = (size_t)64 * lda, strB = (size_t)64 * ldb;

    const int NT = K / BKg;
    #pragma unroll
    for (int t = 0; t < STAGES - 1; t++) {
        if (t < NT) {
            uint32_t sa = sbase + t * STG_BYTES;
            const __nv_bfloat16* a_src = pA + t * BKg;
            const __nv_bfloat16* b_src = pB + t * BKg;
            cp16(sa + sof,        a_src);
            cp16(sa + sof + 8192, a_src + strA);
            #pragma unroll
            for (int i = 0; i < 4; i++)
                cp16(sa + A_BYTES + sof + 8192 * i, b_src + strB * i);
        }
        cp_commit();
    }

    float acc[2][8][4];
    #pragma unroll
    for (int i = 0; i < 2; i++)
        #pragma unroll
        for (int j = 0; j < 8; j++)
            #pragma unroll
            for (int k = 0; k < 4; k++) acc[i][j][k] = 0.f;

    const int aRow = lane & 15, aC = lane >> 4;
    const int bRow = (lane & 7) + ((lane & 16) >> 1), bC = (lane >> 3) & 1;

    for (int t = 0; t < NT; t++) {
        if (t >= NT - (STAGES - 1)) cp_wait<0>(); else cp_wait<STAGES - 2>();
        __syncthreads();
        if (t + STAGES - 1 < NT) {
            int tp = t + STAGES - 1;
            uint32_t sa = sbase + (tp % STAGES) * STG_BYTES;
            const __nv_bfloat16* a_src = pA + tp * BKg;
            const __nv_bfloat16* b_src = pB + tp * BKg;
            cp16(sa + sof,        a_src);
            cp16(sa + sof + 8192, a_src + strA);
            #pragma unroll
            for (int i = 0; i < 4; i++)
                cp16(sa + A_BYTES + sof + 8192 * i, b_src + strB * i);
        }
        cp_commit();
        const uint32_t aS = sbase + (t % STAGES) * STG_BYTES;
        const uint32_t bS = aS + A_BYTES;
        #pragma unroll
        for (int kk = 0; kk < 4; kk++) {
            uint32_t af[2][4], bf[8][2];
            #pragma unroll
            for (int mf = 0; mf < 2; mf++)
                ldm4(af[mf][0], af[mf][1], af[mf][2], af[mf][3],
                     aS + smoff(wmB + mf * 16 + aRow, kk * 2 + aC));
            #pragma unroll
            for (int g = 0; g < 4; g++)
                ldm4(bf[2 * g][0], bf[2 * g][1], bf[2 * g + 1][0], bf[2 * g + 1][1],
                     bS + smoff(wnB + g * 16 + bRow, kk * 2 + bC));
            #pragma unroll
            for (int mf = 0; mf < 2; mf++)
                #pragma unroll
                for (int nf = 0; nf < 8; nf++)
                    mma16816(acc[mf][nf], af[mf], bf[nf]);
        }
    }

    float* Of = (float*)OutP + (size_t)bz * sO;
    __nv_bfloat16* Oh = (__nv_bfloat16*)OutP + (size_t)bz * sO;
    const float* Rz = resid + (size_t)bz * sR;
    #pragma unroll
    for (int mf = 0; mf < 2; mf++) {
        #pragma unroll
        for (int pr = 0; pr < 2; pr++) {
            const int row = m0 + wmB + mf * 16 + (lane >> 2) + pr * 8;
            float rb = 0.f;
            if (MODE == MV || MODE == MP) rb = bias[row];
            #pragma unroll
            for (int nf = 0; nf < 8; nf++) {
                const int col = n0 + wnB + nf * 8 + (lane & 3) * 2;
                float v0 = acc[mf][nf][pr * 2 + 0];
                float v1 = acc[mf][nf][pr * 2 + 1];
                if (MODE == MQ) { v0 = (v0 + bias[col]) * SCALEf; v1 = (v1 + bias[col + 1]) * SCALEf; }
                if (MODE == MK) { v0 += bias[col]; v1 += bias[col + 1]; }
                if (MODE == MV || MODE == MP) { v0 += rb; v1 += rb; }
                const size_t oi = (size_t)row * Nd + col;
                if (MODE == MP) {
                    float2 rrv = *(const float2*)&Rz[oi];
                    *(float2*)&Of[oi] = make_float2(v0 + rrv.x, v1 + rrv.y);
                } else {
                    *(__nv_bfloat162*)&Oh[oi] =
                        __nv_bfloat162(__float2bfloat16(v0), __float2bfloat16(v1));
                }
            }
        }
    }
}

// ---------------- fused Q+K GEMM with resident A panel -----------------------
// A = h[m0:m0+128, 0:512] resident in SMEM (128 KB); weights streamed through
// 3 x 32 KB stages. 16 logical weight-tiles: 0..7 = Wq, 8..15 = Wk.
#define QK_APANEL 131072                 // 8 k-tiles x 16 KB
#define QK_WSTG   32768
#define QK_SMEM   (QK_APANEL + 3 * QK_WSTG)   // 224 KB

__global__ __launch_bounds__(512, 1)
void hgemm_qk(const __nv_bfloat16* __restrict__ H,
              const __nv_bfloat16* __restrict__ Wq, const __nv_bfloat16* __restrict__ Wk,
              __nv_bfloat16* __restrict__ Qo, __nv_bfloat16* __restrict__ Ko,
              const float* __restrict__ bq, const float* __restrict__ bk) {
    extern __shared__ char smem[];
    const uint32_t sbase = s2u(smem);
    const int tid = threadIdx.x, lane = tid & 31, warp = tid >> 5;
    const int wmB = (warp >> 2) * 32, wnB = (warp & 3) * 64;
    const int m0 = blockIdx.y * 128, n0 = blockIdx.x * 256;
    const int bz = blockIdx.z;

    const int rr = tid >> 3, cch = tid & 7;
    const uint32_t sof = smoff(rr, cch);
    const __nv_bfloat16* pH = H + (size_t)bz * Nn * Cc + (size_t)(m0 + rr) * Cc + cch * 8;
    const __nv_bfloat16* pWq = Wq + (size_t)(n0 + rr) * Cc + cch * 8;
    const __nv_bfloat16* pWk = Wk + (size_t)(n0 + rr) * Cc + cch * 8;
    const size_t strA = (size_t)64 * Cc;

    // ---- prologue: full A panel (8 tiles) + weight tile 0, then tile 1
    #pragma unroll
    for (int t = 0; t < 8; t++) {
        uint32_t sa = sbase + t * 16384;
        cp16(sa + sof,        pH + t * BKg);
        cp16(sa + sof + 8192, pH + t * BKg + strA);
    }
    {
        uint32_t sw = sbase + QK_APANEL;           // stage 0
        #pragma unroll
        for (int i = 0; i < 4; i++)
            cp16(sw + sof + 8192 * i, pWq + (size_t)64 * i * Cc);
    }
    cp_commit();                                    // group: A panel + w0
    {
        uint32_t sw = sbase + QK_APANEL + QK_WSTG; // stage 1
        #pragma unroll
        for (int i = 0; i < 4; i++)
            cp16(sw + sof + 8192 * i, pWq + (size_t)64 * i * Cc + BKg);
    }
    cp_commit();                                    // group: w1

    float acc[2][8][4];
    #pragma unroll
    for (int i = 0; i < 2; i++)
        #pragma unroll
        for (int j = 0; j < 8; j++)
            #pragma unroll
            for (int k = 0; k < 4; k++) acc[i][j][k] = 0.f;

    const int aRow = lane & 15, aC = lane >> 4;
    const int bRow = (lane & 7) + ((lane & 16) >> 1), bC = (lane >> 3) & 1;

    for (int T = 0; T < 16; T++) {
        if (T >= 14) cp_wait<0>(); else cp_wait<1>();
        __syncthreads();
        if (T + 2 < 16) {
            int tp = T + 2;
            const __nv_bfloat16* wsrc = (tp < 8) ? (pWq + (tp & 7) * BKg)
                                                 : (pWk + (tp & 7) * BKg);
            uint32_t sw = sbase + QK_APANEL + (tp % 3) * QK_WSTG;
            #pragma unroll
            for (int i = 0; i < 4; i++)
                cp16(sw + sof + 8192 * i, wsrc + (size_t)64 * i * Cc);
        }
        cp_commit();
        const uint32_t aS = sbase + (T & 7) * 16384;
        const uint32_t bS = sbase + QK_APANEL + (T % 3) * QK_WSTG;
        #pragma unroll
        for (int kk = 0; kk < 4; kk++) {
            uint32_t af[2][4], bf[8][2];
            #pragma unroll
            for (int mf = 0; mf < 2; mf++)
                ldm4(af[mf][0], af[mf][1], af[mf][2], af[mf][3],
                     aS + smoff(wmB + mf * 16 + aRow, kk * 2 + aC));
            #pragma unroll
            for (int g = 0; g < 4; g++)
                ldm4(bf[2 * g][0], bf[2 * g][1], bf[2 * g + 1][0], bf[2 * g + 1][1],
                     bS + smoff(wnB + g * 16 + bRow, kk * 2 + bC));
            #pragma unroll
            for (int mf = 0; mf < 2; mf++)
                #pragma unroll
                for (int nf = 0; nf < 8; nf++)
                    mma16816(acc[mf][nf], af[mf], bf[nf]);
        }
        if (T == 7 || T == 15) {
            // epilogue for the finished phase
            const int isQ = (T == 7);
            __nv_bfloat16* Oh = (isQ ? Qo : Ko) + (size_t)bz * Nn * Cc;
            const float* bias = isQ ? bq : bk;
            #pragma unroll
            for (int mf = 0; mf < 2; mf++)
                #pragma unroll
                for (int pr = 0; pr < 2; pr++) {
                    const int row = m0 + wmB + mf * 16 + (lane >> 2) + pr * 8;
                    #pragma unroll
                    for (int nf = 0; nf < 8; nf++) {
                        const int col = n0 + wnB + nf * 8 + (lane & 3) * 2;
                        float v0 = acc[mf][nf][pr * 2 + 0] + bias[col];
                        float v1 = acc[mf][nf][pr * 2 + 1] + bias[col + 1];
                        if (isQ) { v0 *= SCALEf; v1 *= SCALEf; }
                        *(__nv_bfloat162*)&Oh[(size_t)row * Cc + col] =
                            __nv_bfloat162(__float2bfloat16(v0), __float2bfloat16(v1));
                        acc[mf][nf][pr * 2 + 0] = 0.f;
                        acc[mf][nf][pr * 2 + 1] = 0.f;
                    }
                }
        }
    }
}

// ---------------- row softmax (in-place, bf16 rows of 4096) -----------------
__global__ void softmax_row_kernel(__nv_bfloat16* __restrict__ s) {
    __nv_bfloat16* p = s + (size_t)blockIdx.x * Nn;
    const int tid = threadIdx.x;
    float v[16];
    uint4 raw[2];
    #pragma unroll
    for (int h = 0; h < 2; h++) {
        raw[h] = *(const uint4*)(p + (tid + h * 256) * 8);
        const __nv_bfloat16* pb = (const __nv_bfloat16*)&raw[h];
        #pragma unroll
        for (int e = 0; e < 8; e++) v[h * 8 + e] = __bfloat162float(pb[e]);
    }
    float mx = -1e30f;
    #pragma unroll
    for (int i = 0; i < 16; i++) mx = fmaxf(mx, v[i]);
    __shared__ float red[8];
    const int wid = tid >> 5, lane = tid & 31;
    #pragma unroll
    for (int o = 16; o; o >>= 1) mx = fmaxf(mx, __shfl_xor_sync(0xffffffffu, mx, o));
    if (lane == 0) red[wid] = mx;
    __syncthreads();
    mx = red[0];
    #pragma unroll
    for (int i = 1; i < 8; i++) mx = fmaxf(mx, red[i]);
    __syncthreads();
    float sum = 0.f;
    #pragma unroll
    for (int i = 0; i < 16; i++) { v[i] = fexp(v[i] - mx); sum += v[i]; }
    #pragma unroll
    for (int o = 16; o; o >>= 1) sum += __shfl_xor_sync(0xffffffffu, sum, o);
    if (lane == 0) red[wid] = sum;
    __syncthreads();
    sum = 0.f;
    #pragma unroll
    for (int i = 0; i < 8; i++) sum += red[i];
    const float inv = 1.f / sum;
    #pragma unroll
    for (int h = 0; h < 2; h++) {
        uint4 outp;
        __nv_bfloat16* ob = (__nv_bfloat16*)&outp;
        #pragma unroll
        for (int e = 0; e < 8; e++) ob[e] = __float2bfloat16(v[h * 8 + e] * inv);
        *(uint4*)(p + (tid + h * 256) * 8) = outp;
    }
}

// ---------------- launch -----------------------------------------------------
extern "C" void kernel_launch(void* const* d_in, const int* in_sizes, int n_in,
                              void* d_out, int out_size) {
    const float* x  = (const float*)d_in[0];
    const float* gw = (const float*)d_in[1];
    const float* gb = (const float*)d_in[2];
    const float* wq = (const float*)d_in[3];
    const float* bq = (const float*)d_in[4];
    const float* wk = (const float*)d_in[5];
    const float* bk = (const float*)d_in[6];
    const float* wv = (const float*)d_in[7];
    const float* bv = (const float*)d_in[8];
    const float* wp = (const float*)d_in[9];
    const float* bp = (const float*)d_in[10];
    float* out = (float*)d_out;

    __nv_bfloat16 *ht, *qt, *kt, *vv, *ot, *sc, *bwq, *bwk, *bwv, *bwp;
    float* stats;
    cudaGetSymbolAddress((void**)&ht, g_ht);
    cudaGetSymbolAddress((void**)&qt, g_qt);
    cudaGetSymbolAddress((void**)&kt, g_kt);
    cudaGetSymbolAddress((void**)&vv, g_vv);
    cudaGetSymbolAddress((void**)&ot, g_ot);
    cudaGetSymbolAddress((void**)&sc, g_s);
    cudaGetSymbolAddress((void**)&bwq, g_wq);
    cudaGetSymbolAddress((void**)&bwk, g_wk);
    cudaGetSymbolAddress((void**)&bwv, g_wv);
    cudaGetSymbolAddress((void**)&bwp, g_wp);
    cudaGetSymbolAddress((void**)&stats, g_stats);

    cudaFuncSetAttribute(hgemm<MV>, cudaFuncAttributeMaxDynamicSharedMemorySize, GEMM_SMEM);
    cudaFuncSetAttribute(hgemm<MS>, cudaFuncAttributeMaxDynamicSharedMemorySize, GEMM_SMEM);
    cudaFuncSetAttribute(hgemm<MA>, cudaFuncAttributeMaxDynamicSharedMemorySize, GEMM_SMEM);
    cudaFuncSetAttribute(hgemm<MP>, cudaFuncAttributeMaxDynamicSharedMemorySize, GEMM_SMEM);
    cudaFuncSetAttribute(hgemm_qk,  cudaFuncAttributeMaxDynamicSharedMemorySize, QK_SMEM);

    const long long NC_ = (long long)Nn * Cc;
    const long long CN_ = (long long)Cc * Nn;
    const long long NN_ = (long long)Nn * Nn;

    prep_kernel<<<320, 256>>>(wq, wk, wv, wp, bwq, bwk, bwv, bwp, x, stats);
    gn_norm_t_kernel<<<dim3(Nn / 64, Cc / 64, Bb), 256>>>(x, gw, gb, stats, ht);

    // fused q & k: q[n][d] = scale*(h@Wq + bq); k[n][d] = h@Wk + bk
    hgemm_qk<<<dim3(2, 32, Bb), 512, QK_SMEM>>>(ht, bwq, bwk, qt, kt, bq, bk);
    // v[c][n] = Wv[c][:] @ h[n][:] + bv[c]         M=512 N=4096 K=512
    hgemm<MV><<<dim3(16, 4, Bb), 512, GEMM_SMEM>>>(bwv, ht, vv, Cc, Cc, Nn, Cc,
                                                   bv, nullptr, 0, NC_, CN_, 0);
    // s[i][j] = q[i][:] . k[j][:]                  M=4096 N=4096 K=512
    hgemm<MS><<<dim3(16, 32, Bb), 512, GEMM_SMEM>>>(qt, kt, sc, Cc, Cc, Nn, Cc,
                                                    nullptr, nullptr, NC_, NC_, NN_, 0);
    softmax_row_kernel<<<Bb * Nn, 256>>>(sc);
    // o[q][c] = p[q][:] . v[c][:]                  M=4096 N=512 K=4096
    hgemm<MA><<<dim3(2, 32, Bb), 512, GEMM_SMEM>>>(sc, vv, ot, Nn, Nn, Cc, Nn,
                                                   nullptr, nullptr, NN_, CN_, NC_, 0);
    // out[c][n] = Wp[c][:] @ o[n][:] + bp[c] + x   M=512 N=4096 K=512
    hgemm<MP><<<dim3(16, 4, Bb), 512, GEMM_SMEM>>>(bwp, ot, out, Cc, Cc, Nn, Cc,
                                                   bp, x, 0, NC_, CN_, CN_);
}

// round 15
// speedup vs baseline: 1.1174x; 1.0186x over previous
#include <cuda_runtime.h>
#include <cuda_bf16.h>
#include <stdint.h>
#include <math.h>

#define Cc   512
#define Gg   32
#define CPG  16
#define Nn   4096
#define Bb   2
#define EPSf 1e-6f
#define SCALEf 0.04419417382415922f   // 512^-0.5

// ---------------- device scratch (static; no runtime alloc) ----------------
__device__ __nv_bfloat16 g_ht[(size_t)Bb * Nn * Cc];   // h  [b][n][c]
__device__ __nv_bfloat16 g_qt[(size_t)Bb * Nn * Cc];   // q  [b][n][d] (pre-scaled)
__device__ __nv_bfloat16 g_kt[(size_t)Bb * Nn * Cc];   // k  [b][n][d]
__device__ __nv_bfloat16 g_vv[(size_t)Bb * Cc * Nn];   // v  [b][c][n]
__device__ __nv_bfloat16 g_ot[(size_t)Bb * Nn * Cc];   // o  [b][n][c]
__device__ __nv_bfloat16 g_s [(size_t)Bb * Nn * Nn];   // exp(scores) [b][i][j]
__device__ float         g_sum[(size_t)Bb * Nn];       // row sums of exp(scores)
__device__ __nv_bfloat16 g_wq[Cc * Cc], g_wk[Cc * Cc], g_wv[Cc * Cc], g_wp[Cc * Cc];
__device__ float g_stats[Bb * Gg * 2];

// ---------------- helpers ----------------------------------------------------
__device__ __forceinline__ uint32_t s2u(const void* p) {
    return (uint32_t)__cvta_generic_to_shared((void*)p);
}
__device__ __forceinline__ void cp16(uint32_t saddr, const void* gaddr) {
    asm volatile("cp.async.cg.shared.global [%0], [%1], 16;" :: "r"(saddr), "l"(gaddr));
}
__device__ __forceinline__ void cp_commit() {
    asm volatile("cp.async.commit_group;" ::: "memory");
}
template <int N>
__device__ __forceinline__ void cp_wait() {
    asm volatile("cp.async.wait_group %0;" :: "n"(N) : "memory");
}
__device__ __forceinline__ void ldm4(uint32_t& r0, uint32_t& r1, uint32_t& r2, uint32_t& r3,
                                     uint32_t addr) {
    asm volatile("ldmatrix.sync.aligned.m8n8.x4.shared.b16 {%0,%1,%2,%3}, [%4];"
                 : "=r"(r0), "=r"(r1), "=r"(r2), "=r"(r3) : "r"(addr));
}
__device__ __forceinline__ void mma16816(float* d, const uint32_t* a, const uint32_t* b) {
    asm volatile("mma.sync.aligned.m16n8k16.row.col.f32.bf16.bf16.f32 "
                 "{%0,%1,%2,%3}, {%4,%5,%6,%7}, {%8,%9}, {%0,%1,%2,%3};"
                 : "+f"(d[0]), "+f"(d[1]), "+f"(d[2]), "+f"(d[3])
                 : "r"(a[0]), "r"(a[1]), "r"(a[2]), "r"(a[3]), "r"(b[0]), "r"(b[1]));
}
// SW128 swizzle for 128B rows: element (row, 16B-chunk c in 0..7)
__device__ __forceinline__ uint32_t smoff(int row, int c) {
    return (uint32_t)(row * 128 + ((c ^ (row & 7)) << 4));
}
__device__ __forceinline__ float fexp(float x) {
    x = fmaxf(x, -87.f);
    float z  = x * 1.4426950408889634f;
    float zi = rintf(z);
    float zf = z - zi;
    float r = 1.33978439e-3f;
    r = fmaf(r, zf, 9.67580429e-3f);
    r = fmaf(r, zf, 5.55041087e-2f);
    r = fmaf(r, zf, 2.40226507e-1f);
    r = fmaf(r, zf, 6.93147182e-1f);
    r = fmaf(r, zf, 1.0f);
    return r * __int_as_float(((int)zi + 127) << 23);
}

// ---------------- fused: weight fp32->bf16, GroupNorm stats, zero row-sums ---
// blocks [0,256): weight convert; blocks [256,320): stats (+ zero 128 sums each)
__global__ void prep_kernel(const float* __restrict__ wq, const float* __restrict__ wk,
                            const float* __restrict__ wv, const float* __restrict__ wp,
                            __nv_bfloat16* oq, __nv_bfloat16* ok,
                            __nv_bfloat16* ov, __nv_bfloat16* op,
                            const float* __restrict__ x, float* __restrict__ stats,
                            float* __restrict__ sums) {
    if (blockIdx.x < 256) {
        int i = blockIdx.x * blockDim.x + threadIdx.x;
        const float4* src[4] = {(const float4*)wq, (const float4*)wk,
                                (const float4*)wv, (const float4*)wp};
        __nv_bfloat162* dst[4] = {(__nv_bfloat162*)oq, (__nv_bfloat162*)ok,
                                  (__nv_bfloat162*)ov, (__nv_bfloat162*)op};
        #pragma unroll
        for (int m = 0; m < 4; m++) {
            float4 v = src[m][i];
            dst[m][i * 2 + 0] = __nv_bfloat162(__float2bfloat16(v.x), __float2bfloat16(v.y));
            dst[m][i * 2 + 1] = __nv_bfloat162(__float2bfloat16(v.z), __float2bfloat16(v.w));
        }
        return;
    }
    const int bg = blockIdx.x - 256;
    if (threadIdx.x < 128) sums[bg * 128 + threadIdx.x] = 0.f;   // 64 blks x 128 = 8192
    const size_t base = (size_t)bg * CPG * Nn;
    const int n_el = CPG * Nn;
    float s = 0.f, ss = 0.f;
    for (int i = threadIdx.x; i < n_el; i += blockDim.x) {
        float v = x[base + i];
        s += v; ss += v * v;
    }
    __shared__ float red[16];
    #pragma unroll
    for (int o = 16; o; o >>= 1) {
        s  += __shfl_down_sync(0xffffffffu, s,  o);
        ss += __shfl_down_sync(0xffffffffu, ss, o);
    }
    const int wid = threadIdx.x >> 5, lane = threadIdx.x & 31;
    if (lane == 0) { red[wid] = s; red[8 + wid] = ss; }
    __syncthreads();
    if (threadIdx.x == 0) {
        float ts = 0.f, tss = 0.f;
        #pragma unroll
        for (int i = 0; i < 8; i++) { ts += red[i]; tss += red[8 + i]; }
        float mu = ts / (float)n_el;
        float var = tss / (float)n_el - mu * mu;
        stats[bg * 2 + 0] = mu;
        stats[bg * 2 + 1] = rsqrtf(var + EPSf);
    }
}

// ---------------- normalize + transpose x[b][c][n] -> h[b][n][c] bf16 -------
__global__ void gn_norm_t_kernel(const float* __restrict__ x,
                                 const float* __restrict__ w, const float* __restrict__ b,
                                 const float* __restrict__ stats,
                                 __nv_bfloat16* __restrict__ ht) {
    __shared__ float tile[64][65];
    const int n0 = blockIdx.x * 64, c0 = blockIdx.y * 64, bz = blockIdx.z;
    const int tid = threadIdx.x;
    const float* xb = x + (size_t)bz * Cc * Nn;
    #pragma unroll
    for (int i = 0; i < 4; i++) {
        int vi = tid + i * 256;
        int r = vi >> 4, seg = (vi & 15) * 4;
        float4 v = *(const float4*)&xb[(size_t)(c0 + r) * Nn + n0 + seg];
        tile[r][seg + 0] = v.x; tile[r][seg + 1] = v.y;
        tile[r][seg + 2] = v.z; tile[r][seg + 3] = v.w;
    }
    __syncthreads();
    const int nr = tid >> 2, cs = (tid & 3) * 16;
    __nv_bfloat16* hrow = ht + ((size_t)bz * Nn + n0 + nr) * Cc + c0;
    #pragma unroll
    for (int c = 0; c < 16; c++) {
        int cg = cs + c, ch = c0 + cg;
        int sidx = (bz * Gg + (ch >> 4)) * 2;
        float mu = stats[sidx], inv = stats[sidx + 1];
        hrow[cg] = __float2bfloat16((tile[cg][nr] - mu) * inv * w[ch] + b[ch]);
    }
}

// ---------------- generic bf16 HMMA GEMM (R9 config) -------------------------
// Tile 128(M) x 256(N) x 64(K), 512 threads (16 warps, 4x4), warp tile 32x64.
// MS: epilogue computes exp(acc), writes bf16, atomically accumulates row sums.
// MA: epilogue multiplies by 1/rowsum.
enum { MQ = 0, MK = 1, MV = 2, MS = 3, MA = 4, MP = 5 };
#define BKg 64
#define STAGES 3
#define A_BYTES 16384
#define B_BYTES 32768
#define STG_BYTES (A_BYTES + B_BYTES)
#define GEMM_SMEM (STAGES * STG_BYTES)       // 144 KB

template <int MODE>
__global__ __launch_bounds__(512, 1)
void hgemm(const __nv_bfloat16* __restrict__ A, const __nv_bfloat16* __restrict__ B,
           void* __restrict__ OutP, int lda, int ldb, int Nd, int K,
           const float* __restrict__ bias, const float* __restrict__ resid,
           long long sA, long long sB, long long sO, long long sR) {
    extern __shared__ char smem[];
    const uint32_t sbase = s2u(smem);
    const int tid = threadIdx.x, lane = tid & 31, warp = tid >> 5;
    const int wmB = (warp >> 2) * 32, wnB = (warp & 3) * 64;
    const int m0 = blockIdx.y * 128, n0 = blockIdx.x * 256;
    const int bz = blockIdx.z;

    const int rr = tid >> 3, cch = tid & 7;
    const uint32_t sof = smoff(rr, cch);
    const __nv_bfloat16* pA = A + (size_t)bz * sA + (size_t)(m0 + rr) * lda + cch * 8;
    const __nv_bfloat16* pB = B + (size_t)bz * sB + (size_t)(n0 + rr) * ldb + cch * 8;
    const size_t strA = (size_t)64 * lda, strB = (size_t)64 * ldb;

    const int NT = K / BKg;
    #pragma unroll
    for (int t = 0; t < STAGES - 1; t++) {
        if (t < NT) {
            uint32_t sa = sbase + t * STG_BYTES;
            const __nv_bfloat16* a_src = pA + t * BKg;
            const __nv_bfloat16* b_src = pB + t * BKg;
            cp16(sa + sof,        a_src);
            cp16(sa + sof + 8192, a_src + strA);
            #pragma unroll
            for (int i = 0; i < 4; i++)
                cp16(sa + A_BYTES + sof + 8192 * i, b_src + strB * i);
        }
        cp_commit();
    }

    float acc[2][8][4];
    #pragma unroll
    for (int i = 0; i < 2; i++)
        #pragma unroll
        for (int j = 0; j < 8; j++)
            #pragma unroll
            for (int k = 0; k < 4; k++) acc[i][j][k] = 0.f;

    const int aRow = lane & 15, aC = lane >> 4;
    const int bRow = (lane & 7) + ((lane & 16) >> 1), bC = (lane >> 3) & 1;

    for (int t = 0; t < NT; t++) {
        if (t >= NT - (STAGES - 1)) cp_wait<0>(); else cp_wait<STAGES - 2>();
        __syncthreads();
        if (t + STAGES - 1 < NT) {
            int tp = t + STAGES - 1;
            uint32_t sa = sbase + (tp % STAGES) * STG_BYTES;
            const __nv_bfloat16* a_src = pA + tp * BKg;
            const __nv_bfloat16* b_src = pB + tp * BKg;
            cp16(sa + sof,        a_src);
            cp16(sa + sof + 8192, a_src + strA);
            #pragma unroll
            for (int i = 0; i < 4; i++)
                cp16(sa + A_BYTES + sof + 8192 * i, b_src + strB * i);
        }
        cp_commit();
        const uint32_t aS = sbase + (t % STAGES) * STG_BYTES;
        const uint32_t bS = aS + A_BYTES;
        #pragma unroll
        for (int kk = 0; kk < 4; kk++) {
            uint32_t af[2][4], bf[8][2];
            #pragma unroll
            for (int mf = 0; mf < 2; mf++)
                ldm4(af[mf][0], af[mf][1], af[mf][2], af[mf][3],
                     aS + smoff(wmB + mf * 16 + aRow, kk * 2 + aC));
            #pragma unroll
            for (int g = 0; g < 4; g++)
                ldm4(bf[2 * g][0], bf[2 * g][1], bf[2 * g + 1][0], bf[2 * g + 1][1],
                     bS + smoff(wnB + g * 16 + bRow, kk * 2 + bC));
            #pragma unroll
            for (int mf = 0; mf < 2; mf++)
                #pragma unroll
                for (int nf = 0; nf < 8; nf++)
                    mma16816(acc[mf][nf], af[mf], bf[nf]);
        }
    }

    float* Of = (float*)OutP + (size_t)bz * sO;
    __nv_bfloat16* Oh = (__nv_bfloat16*)OutP + (size_t)bz * sO;
    const float* Rz = resid + (size_t)bz * sR;
    #pragma unroll
    for (int mf = 0; mf < 2; mf++) {
        #pragma unroll
        for (int pr = 0; pr < 2; pr++) {
            const int row = m0 + wmB + mf * 16 + (lane >> 2) + pr * 8;
            float rb = 0.f;
            if (MODE == MV || MODE == MP) rb = bias[row];
            float cr = 1.f, rsum = 0.f;
            if (MODE == MA) cr = 1.f / resid[(size_t)bz * Nn + row];
            #pragma unroll
            for (int nf = 0; nf < 8; nf++) {
                const int col = n0 + wnB + nf * 8 + (lane & 3) * 2;
                float v0 = acc[mf][nf][pr * 2 + 0];
                float v1 = acc[mf][nf][pr * 2 + 1];
                if (MODE == MQ) { v0 = (v0 + bias[col]) * SCALEf; v1 = (v1 + bias[col + 1]) * SCALEf; }
                if (MODE == MK) { v0 += bias[col]; v1 += bias[col + 1]; }
                if (MODE == MV || MODE == MP) { v0 += rb; v1 += rb; }
                if (MODE == MS) { v0 = fexp(v0); v1 = fexp(v1); rsum += v0 + v1; }
                if (MODE == MA) { v0 *= cr; v1 *= cr; }
                const size_t oi = (size_t)row * Nd + col;
                if (MODE == MP) {
                    float2 rrv = *(const float2*)&Rz[oi];
                    *(float2*)&Of[oi] = make_float2(v0 + rrv.x, v1 + rrv.y);
                } else {
                    *(__nv_bfloat162*)&Oh[oi] =
                        __nv_bfloat162(__float2bfloat16(v0), __float2bfloat16(v1));
                }
            }
            if (MODE == MS) {
                rsum += __shfl_xor_sync(0xffffffffu, rsum, 1);
                rsum += __shfl_xor_sync(0xffffffffu, rsum, 2);
                if ((lane & 3) == 0)
                    atomicAdd((float*)&resid[(size_t)bz * Nn + row], rsum);
            }
        }
    }
}

// ---------------- fused Q+K GEMM with resident A panel -----------------------
#define QK_APANEL 131072                 // 8 k-tiles x 16 KB
#define QK_WSTG   32768
#define QK_SMEM   (QK_APANEL + 3 * QK_WSTG)   // 224 KB

__global__ __launch_bounds__(512, 1)
void hgemm_qk(const __nv_bfloat16* __restrict__ H,
              const __nv_bfloat16* __restrict__ Wq, const __nv_bfloat16* __restrict__ Wk,
              __nv_bfloat16* __restrict__ Qo, __nv_bfloat16* __restrict__ Ko,
              const float* __restrict__ bq, const float* __restrict__ bk) {
    extern __shared__ char smem[];
    const uint32_t sbase = s2u(smem);
    const int tid = threadIdx.x, lane = tid & 31, warp = tid >> 5;
    const int wmB = (warp >> 2) * 32, wnB = (warp & 3) * 64;
    const int m0 = blockIdx.y * 128, n0 = blockIdx.x * 256;
    const int bz = blockIdx.z;

    const int rr = tid >> 3, cch = tid & 7;
    const uint32_t sof = smoff(rr, cch);
    const __nv_bfloat16* pH = H + (size_t)bz * Nn * Cc + (size_t)(m0 + rr) * Cc + cch * 8;
    const __nv_bfloat16* pWq = Wq + (size_t)(n0 + rr) * Cc + cch * 8;
    const __nv_bfloat16* pWk = Wk + (size_t)(n0 + rr) * Cc + cch * 8;
    const size_t strA = (size_t)64 * Cc;

    #pragma unroll
    for (int t = 0; t < 8; t++) {
        uint32_t sa = sbase + t * 16384;
        cp16(sa + sof,        pH + t * BKg);
        cp16(sa + sof + 8192, pH + t * BKg + strA);
    }
    {
        uint32_t sw = sbase + QK_APANEL;
        #pragma unroll
        for (int i = 0; i < 4; i++)
            cp16(sw + sof + 8192 * i, pWq + (size_t)64 * i * Cc);
    }
    cp_commit();
    {
        uint32_t sw = sbase + QK_APANEL + QK_WSTG;
        #pragma unroll
        for (int i = 0; i < 4; i++)
            cp16(sw + sof + 8192 * i, pWq + (size_t)64 * i * Cc + BKg);
    }
    cp_commit();

    float acc[2][8][4];
    #pragma unroll
    for (int i = 0; i < 2; i++)
        #pragma unroll
        for (int j = 0; j < 8; j++)
            #pragma unroll
            for (int k = 0; k < 4; k++) acc[i][j][k] = 0.f;

    const int aRow = lane & 15, aC = lane >> 4;
    const int bRow = (lane & 7) + ((lane & 16) >> 1), bC = (lane >> 3) & 1;

    for (int T = 0; T < 16; T++) {
        if (T >= 14) cp_wait<0>(); else cp_wait<1>();
        __syncthreads();
        if (T + 2 < 16) {
            int tp = T + 2;
            const __nv_bfloat16* wsrc = (tp < 8) ? (pWq + (tp & 7) * BKg)
                                                 : (pWk + (tp & 7) * BKg);
            uint32_t sw = sbase + QK_APANEL + (tp % 3) * QK_WSTG;
            #pragma unroll
            for (int i = 0; i < 4; i++)
                cp16(sw + sof + 8192 * i, wsrc + (size_t)64 * i * Cc);
        }
        cp_commit();
        const uint32_t aS = sbase + (T & 7) * 16384;
        const uint32_t bS = sbase + QK_APANEL + (T % 3) * QK_WSTG;
        #pragma unroll
        for (int kk = 0; kk < 4; kk++) {
            uint32_t af[2][4], bf[8][2];
            #pragma unroll
            for (int mf = 0; mf < 2; mf++)
                ldm4(af[mf][0], af[mf][1], af[mf][2], af[mf][3],
                     aS + smoff(wmB + mf * 16 + aRow, kk * 2 + aC));
            #pragma unroll
            for (int g = 0; g < 4; g++)
                ldm4(bf[2 * g][0], bf[2 * g][1], bf[2 * g + 1][0], bf[2 * g + 1][1],
                     bS + smoff(wnB + g * 16 + bRow, kk * 2 + bC));
            #pragma unroll
            for (int mf = 0; mf < 2; mf++)
                #pragma unroll
                for (int nf = 0; nf < 8; nf++)
                    mma16816(acc[mf][nf], af[mf], bf[nf]);
        }
        if (T == 7 || T == 15) {
            const int isQ = (T == 7);
            __nv_bfloat16* Oh = (isQ ? Qo : Ko) + (size_t)bz * Nn * Cc;
            const float* bias = isQ ? bq : bk;
            #pragma unroll
            for (int mf = 0; mf < 2; mf++)
                #pragma unroll
                for (int pr = 0; pr < 2; pr++) {
                    const int row = m0 + wmB + mf * 16 + (lane >> 2) + pr * 8;
                    #pragma unroll
                    for (int nf = 0; nf < 8; nf++) {
                        const int col = n0 + wnB + nf * 8 + (lane & 3) * 2;
                        float v0 = acc[mf][nf][pr * 2 + 0] + bias[col];
                        float v1 = acc[mf][nf][pr * 2 + 1] + bias[col + 1];
                        if (isQ) { v0 *= SCALEf; v1 *= SCALEf; }
                        *(__nv_bfloat162*)&Oh[(size_t)row * Cc + col] =
                            __nv_bfloat162(__float2bfloat16(v0), __float2bfloat16(v1));
                        acc[mf][nf][pr * 2 + 0] = 0.f;
                        acc[mf][nf][pr * 2 + 1] = 0.f;
                    }
                }
        }
    }
}

// ---------------- launch -----------------------------------------------------
extern "C" void kernel_launch(void* const* d_in, const int* in_sizes, int n_in,
                              void* d_out, int out_size) {
    const float* x  = (const float*)d_in[0];
    const float* gw = (const float*)d_in[1];
    const float* gb = (const float*)d_in[2];
    const float* wq = (const float*)d_in[3];
    const float* bq = (const float*)d_in[4];
    const float* wk = (const float*)d_in[5];
    const float* bk = (const float*)d_in[6];
    const float* wv = (const float*)d_in[7];
    const float* bv = (const float*)d_in[8];
    const float* wp = (const float*)d_in[9];
    const float* bp = (const float*)d_in[10];
    float* out = (float*)d_out;

    __nv_bfloat16 *ht, *qt, *kt, *vv, *ot, *sc, *bwq, *bwk, *bwv, *bwp;
    float *stats, *sums;
    cudaGetSymbolAddress((void**)&ht, g_ht);
    cudaGetSymbolAddress((void**)&qt, g_qt);
    cudaGetSymbolAddress((void**)&kt, g_kt);
    cudaGetSymbolAddress((void**)&vv, g_vv);
    cudaGetSymbolAddress((void**)&ot, g_ot);
    cudaGetSymbolAddress((void**)&sc, g_s);
    cudaGetSymbolAddress((void**)&sums, g_sum);
    cudaGetSymbolAddress((void**)&bwq, g_wq);
    cudaGetSymbolAddress((void**)&bwk, g_wk);
    cudaGetSymbolAddress((void**)&bwv, g_wv);
    cudaGetSymbolAddress((void**)&bwp, g_wp);
    cudaGetSymbolAddress((void**)&stats, g_stats);

    cudaFuncSetAttribute(hgemm<MV>, cudaFuncAttributeMaxDynamicSharedMemorySize, GEMM_SMEM);
    cudaFuncSetAttribute(hgemm<MS>, cudaFuncAttributeMaxDynamicSharedMemorySize, GEMM_SMEM);
    cudaFuncSetAttribute(hgemm<MA>, cudaFuncAttributeMaxDynamicSharedMemorySize, GEMM_SMEM);
    cudaFuncSetAttribute(hgemm<MP>, cudaFuncAttributeMaxDynamicSharedMemorySize, GEMM_SMEM);
    cudaFuncSetAttribute(hgemm_qk,  cudaFuncAttributeMaxDynamicSharedMemorySize, QK_SMEM);

    const long long NC_ = (long long)Nn * Cc;
    const long long CN_ = (long long)Cc * Nn;
    const long long NN_ = (long long)Nn * Nn;

    prep_kernel<<<320, 256>>>(wq, wk, wv, wp, bwq, bwk, bwv, bwp, x, stats, sums);
    gn_norm_t_kernel<<<dim3(Nn / 64, Cc / 64, Bb), 256>>>(x, gw, gb, stats, ht);

    // fused q & k: q[n][d] = scale*(h@Wq + bq); k[n][d] = h@Wk + bk
    hgemm_qk<<<dim3(2, 32, Bb), 512, QK_SMEM>>>(ht, bwq, bwk, qt, kt, bq, bk);
    // v[c][n] = Wv[c][:] @ h[n][:] + bv[c]                  M=512 N=4096 K=512
    hgemm<MV><<<dim3(16, 4, Bb), 512, GEMM_SMEM>>>(bwv, ht, vv, Cc, Cc, Nn, Cc,
                                                   bv, nullptr, 0, NC_, CN_, 0);
    // e[i][j] = exp(q[i]·k[j]); sums[i] += row partials      M=4096 N=4096 K=512
    hgemm<MS><<<dim3(16, 32, Bb), 512, GEMM_SMEM>>>(qt, kt, sc, Cc, Cc, Nn, Cc,
                                                    nullptr, sums, NC_, NC_, NN_, 0);
    // o[q][c] = (1/sums[q]) * e[q][:] . v[c][:]              M=4096 N=512 K=4096
    hgemm<MA><<<dim3(2, 32, Bb), 512, GEMM_SMEM>>>(sc, vv, ot, Nn, Nn, Cc, Nn,
                                                   nullptr, sums, NN_, CN_, NC_, 0);
    // out[c][n] = Wp[c][:] @ o[n][:] + bp[c] + x             M=512 N=4096 K=512
    hgemm<MP><<<dim3(16, 4, Bb), 512, GEMM_SMEM>>>(bwp, ot, out, Cc, Cc, Nn, Cc,
                                                   bp, x, 0, NC_, CN_, CN_);
}